// round 6
// baseline (speedup 1.0000x reference)
#include <cuda_runtime.h>
#include <cuda_fp16.h>
#include <mma.h>
#include <math.h>
#include <cstdint>

using namespace nvcuda;

#define Bdim 32
#define Tdim 32
#define Sdim 64
#define Hdim 1024
#define Edim 512
#define Vdim 32000
#define G3   3072
#define KX   1536
#define MROWS (Tdim*Bdim)
#define NBLK  (Vdim/64)
#define SCANB 96          // persistent scan grid (all co-resident, < 148 SMs)
#define SCANT 256

// ---------------------------------------------------------------------------
// Persistent device scratch
// ---------------------------------------------------------------------------
__device__ __align__(16) __half d_wih0H[G3*KX];
__device__ __align__(16) __half d_wih0L[G3*KX];
__device__ __align__(16) __half d_whh0H[G3*Hdim];
__device__ __align__(16) __half d_whh0L[G3*Hdim];
__device__ __align__(16) __half d_wih1H[G3*Hdim];
__device__ __align__(16) __half d_wih1L[G3*Hdim];
__device__ __align__(16) __half d_whh1H[G3*Hdim];
__device__ __align__(16) __half d_whh1L[G3*Hdim];
__device__ __align__(16) __half d_WaH [Hdim*Hdim];
__device__ __align__(16) __half d_WaL [Hdim*Hdim];
__device__ __align__(16) __half d_WoutH[Hdim*2*Hdim];
__device__ __align__(16) __half d_WoutL[Hdim*2*Hdim];
__device__ __align__(16) __half d_Wgen[(size_t)Vdim*Hdim];
__device__ __align__(16) __half d_XH  [Tdim*Bdim*KX];
__device__ __align__(16) __half d_XL  [Tdim*Bdim*KX];
__device__ __align__(16) __half d_h0H [Bdim*Hdim];
__device__ __align__(16) __half d_h0L [Bdim*Hdim];
__device__ __align__(16) __half d_h1H [Bdim*Hdim];
__device__ __align__(16) __half d_h1L [Bdim*Hdim];
__device__ float  d_h0f[Bdim*Hdim];
__device__ float  d_h1f[Bdim*Hdim];
__device__ float  d_gi [Bdim*G3];
__device__ float  d_gh [Bdim*G3];
__device__ float  d_qP [4*Bdim*Hdim];
__device__ float  d_oP [4*Bdim*Hdim];
__device__ __align__(16) __half d_yH  [Bdim*2*Hdim];
__device__ __align__(16) __half d_yL  [Bdim*2*Hdim];
__device__ float  d_outf[Bdim*Hdim];
__device__ __align__(16) __half d_OutAll[MROWS*Hdim];
__device__ float  d_partM[MROWS*NBLK];
__device__ float  d_partS[MROWS*NBLK];
__device__ float  d_lse  [MROWS];

// software grid barrier state
__device__ unsigned g_cnt;
__device__ unsigned g_gen;

__device__ __forceinline__ void split_write(float v, __half* hi, __half* lo) {
    __half h = __float2half_rn(v);
    *hi = h;
    *lo = __float2half_rn(v - __half2float(h));
}

__device__ __forceinline__ void cp16(void* sdst, const void* gsrc) {
    unsigned int s = (unsigned int)__cvta_generic_to_shared(sdst);
    asm volatile("cp.async.cg.shared.global [%0], [%1], 16;\n" :: "r"(s), "l"(gsrc));
}
#define CP_COMMIT() asm volatile("cp.async.commit_group;\n" ::: "memory")
#define CP_WAIT(n)  asm volatile("cp.async.wait_group %0;\n" :: "n"(n) : "memory")

// ---------------------------------------------------------------------------
__global__ void k_reset() { g_cnt = 0; g_gen = 0; }

__global__ void k_f2h_split(const float* __restrict__ s, __half* __restrict__ hi,
                            __half* __restrict__ lo, int n) {
    int i = blockIdx.x * blockDim.x + threadIdx.x;
    if (i < n) split_write(s[i], hi + i, lo + i);
}

__global__ void k_f2h(const float* __restrict__ s, __half* __restrict__ d, int n2) {
    int i = blockIdx.x * blockDim.x + threadIdx.x;
    if (i < n2) {
        float2 v = ((const float2*)s)[i];
        ((half2*)d)[i] = __floats2half2_rn(v.x, v.y);
    }
}

__global__ void k_embed(const int* __restrict__ wids, const int* __restrict__ sids,
                        const float* __restrict__ wemb, const float* __restrict__ semb) {
    int t = blockIdx.x, b = blockIdx.y;
    int wid = wids[b*Tdim + t];
    int sid = sids[b*Tdim + t];
    size_t base = (size_t)(t*Bdim + b)*KX;
    const float* wr = wemb + (size_t)wid*Edim;
    const float* sr = semb + (size_t)sid*Edim;
    for (int e = threadIdx.x; e < Edim; e += blockDim.x)
        split_write(wr[e] + sr[e], d_XH + base + e, d_XL + base + e);
}

__global__ void k_init(const float* __restrict__ hidden, const float* __restrict__ pout) {
    int i = blockIdx.x*blockDim.x + threadIdx.x;
    if (i >= Bdim*Hdim) return;
    int b = i / Hdim, j = i % Hdim;
    float h0 = hidden[i];
    float h1 = hidden[Bdim*Hdim + i];
    d_h0f[i] = h0;  d_h1f[i] = h1;
    split_write(h0, d_h0H + i, d_h0L + i);
    split_write(h1, d_h1H + i, d_h1L + i);
    size_t xo = (size_t)b*KX + Edim + j;
    split_write(pout[i], d_XH + xo, d_XL + xo);
}

// ---------------------------------------------------------------------------
// Fused persistent scan kernel: all 32 timesteps, software grid barriers.
// ---------------------------------------------------------------------------
__device__ __forceinline__ void gbar(unsigned& mygen) {
    __syncthreads();
    if (threadIdx.x == 0) {
        mygen++;
        __threadfence();
        unsigned old = atomicAdd(&g_cnt, 1);
        if (old == SCANB - 1) {
            g_cnt = 0;
            __threadfence();
            atomicExch(&g_gen, mygen);
        } else {
            volatile unsigned* gp = &g_gen;
            while (*gp < mygen) __nanosleep(32);
        }
        __threadfence();
    }
    __syncthreads();
}

// Y[0:32, n0:n0+64] = XH/XL[32,K] @ (WH/WL[N,K])^T  (split-fp16, full K)
template<int KDIM>
__device__ __forceinline__ void gemm_tile_colB(
    const __half* __restrict__ XH, const __half* __restrict__ XL,
    const __half* __restrict__ WH, const __half* __restrict__ WL,
    float* __restrict__ Y, int Nstride, int n0, int warp)
{
    int m = warp & 1, nq = warp >> 1;
    int n = n0 + nq * 16;
    wmma::fragment<wmma::matrix_a,16,16,16,__half,wmma::row_major> aH, aL;
    wmma::fragment<wmma::matrix_b,16,16,16,__half,wmma::col_major> bH, bL;
    wmma::fragment<wmma::accumulator,16,16,16,float> c;
    wmma::fill_fragment(c, 0.f);
    #pragma unroll 4
    for (int k = 0; k < KDIM; k += 16) {
        wmma::load_matrix_sync(aH, XH + (size_t)(m*16)*KDIM + k, KDIM);
        wmma::load_matrix_sync(aL, XL + (size_t)(m*16)*KDIM + k, KDIM);
        wmma::load_matrix_sync(bH, WH + (size_t)n*KDIM + k, KDIM);
        wmma::load_matrix_sync(bL, WL + (size_t)n*KDIM + k, KDIM);
        wmma::mma_sync(c, aH, bH, c);
        wmma::mma_sync(c, aH, bL, c);
        wmma::mma_sync(c, aL, bH, c);
    }
    wmma::store_matrix_sync(Y + (size_t)(m*16)*Nstride + n, c, Nstride, wmma::mem_row_major);
}

__device__ __forceinline__ void gate_phase(
    const float* __restrict__ gi, const float* __restrict__ gh,
    const float* __restrict__ bih, const float* __restrict__ bhh,
    float* __restrict__ hf, __half* __restrict__ hH, __half* __restrict__ hL,
    bool writeY, int gtid)
{
    for (int i = gtid; i < Bdim*Hdim; i += SCANB*SCANT) {
        int b = i >> 10, j = i & 1023;
        size_t o0 = (size_t)b*G3 + j;
        float r = 1.f/(1.f + expf(-(gi[o0]        + bih[j]        + gh[o0]        + bhh[j])));
        float z = 1.f/(1.f + expf(-(gi[o0+Hdim]   + bih[Hdim+j]   + gh[o0+Hdim]   + bhh[Hdim+j])));
        float n = tanhf(gi[o0+2*Hdim] + bih[2*Hdim+j] + r*(gh[o0+2*Hdim] + bhh[2*Hdim+j]));
        float h = (1.f - z)*n + z*hf[i];
        hf[i] = h;
        split_write(h, hH + i, hL + i);
        if (writeY) {
            size_t yo = (size_t)b*2*Hdim + Hdim + j;
            split_write(h, d_yH + yo, d_yL + yo);
        }
    }
}

__global__ void __launch_bounds__(SCANT, 1)
k_scan(const float* __restrict__ bih0, const float* __restrict__ bhh0,
       const float* __restrict__ bih1, const float* __restrict__ bhh1,
       const float* __restrict__ context)
{
    const int blk = blockIdx.x;
    const int tid = threadIdx.x;
    const int warp = tid >> 5, lane = tid & 31;
    const int gtid = blk*SCANT + tid;
    unsigned mygen = 0;
    __shared__ float s_q[Hdim];
    __shared__ float s_sc[Sdim];

    for (int t = 0; t < Tdim; ++t) {
        const __half* XtH = d_XH + (size_t)t*Bdim*KX;
        const __half* XtL = d_XL + (size_t)t*Bdim*KX;

        // A: layer-0 GEMMs
        if (blk < 48)
            gemm_tile_colB<KX>(XtH, XtL, d_wih0H, d_wih0L, d_gi, G3, blk*64, warp);
        else
            gemm_tile_colB<Hdim>(d_h0H, d_h0L, d_whh0H, d_whh0L, d_gh, G3, (blk-48)*64, warp);
        gbar(mygen);

        // B: gate0
        gate_phase(d_gi, d_gh, bih0, bhh0, d_h0f, d_h0H, d_h0L, false, gtid);
        gbar(mygen);

        // C: layer-1 GEMMs
        if (blk < 48)
            gemm_tile_colB<Hdim>(d_h0H, d_h0L, d_wih1H, d_wih1L, d_gi, G3, blk*64, warp);
        else
            gemm_tile_colB<Hdim>(d_h1H, d_h1L, d_whh1H, d_whh1L, d_gh, G3, (blk-48)*64, warp);
        gbar(mygen);

        // D: gate1 (also writes y[:, H:2H])
        gate_phase(d_gi, d_gh, bih1, bhh1, d_h1f, d_h1H, d_h1L, true, gtid);
        gbar(mygen);

        // E: q = h1 @ W_a  (row-major B), 64 blocks, 4-way split-K
        if (blk < 64) {
            int nt = blk & 15, ks = blk >> 4;
            int m = warp & 1, nq = warp >> 1;
            int n = nt*64 + nq*16;
            int k0 = ks*256;
            wmma::fragment<wmma::matrix_a,16,16,16,__half,wmma::row_major> aH, aL;
            wmma::fragment<wmma::matrix_b,16,16,16,__half,wmma::row_major> bH, bL;
            wmma::fragment<wmma::accumulator,16,16,16,float> c;
            wmma::fill_fragment(c, 0.f);
            #pragma unroll 4
            for (int k = k0; k < k0 + 256; k += 16) {
                wmma::load_matrix_sync(aH, d_h1H + (size_t)(m*16)*Hdim + k, Hdim);
                wmma::load_matrix_sync(aL, d_h1L + (size_t)(m*16)*Hdim + k, Hdim);
                wmma::load_matrix_sync(bH, d_WaH + (size_t)k*Hdim + n, Hdim);
                wmma::load_matrix_sync(bL, d_WaL + (size_t)k*Hdim + n, Hdim);
                wmma::mma_sync(c, aH, bH, c);
                wmma::mma_sync(c, aH, bL, c);
                wmma::mma_sync(c, aL, bH, c);
            }
            wmma::store_matrix_sync(d_qP + (size_t)ks*Bdim*Hdim + (size_t)(m*16)*Hdim + n,
                                    c, Hdim, wmma::mem_row_major);
        }
        gbar(mygen);

        // F: attention (blocks 0..31, one per batch row)
        if (blk < Bdim) {
            int b = blk;
            for (int j = tid; j < Hdim; j += SCANT) {
                size_t o = (size_t)b*Hdim + j;
                const size_t PS = (size_t)Bdim*Hdim;
                s_q[j] = d_qP[o] + d_qP[PS + o] + d_qP[2*PS + o] + d_qP[3*PS + o];
            }
            __syncthreads();
            for (int s = warp; s < Sdim; s += 8) {
                const float* cr = context + (size_t)(b*Sdim + s)*Hdim;
                float sum = 0.f;
                for (int j = lane; j < Hdim; j += 32) sum += s_q[j]*cr[j];
                #pragma unroll
                for (int o = 16; o; o >>= 1) sum += __shfl_xor_sync(0xffffffffu, sum, o);
                if (!lane) s_sc[s] = sum;
            }
            __syncthreads();
            float m = -1e30f;
            for (int s = 0; s < Sdim; s++) m = fmaxf(m, s_sc[s]);
            float ssum = 0.f;
            for (int s = 0; s < Sdim; s++) ssum += expf(s_sc[s] - m);
            __syncthreads();
            if (tid < Sdim) s_sc[tid] = expf(s_sc[tid] - m) / ssum;
            __syncthreads();
            const float* cb = context + (size_t)b*Sdim*Hdim;
            for (int j = tid; j < Hdim; j += SCANT) {
                float acc = 0.f;
                #pragma unroll 8
                for (int s = 0; s < Sdim; s++) acc += s_sc[s]*cb[(size_t)s*Hdim + j];
                size_t yo = (size_t)b*2*Hdim + j;
                split_write(acc, d_yH + yo, d_yL + yo);
            }
            __syncthreads();
        }
        gbar(mygen);

        // G: out partials = y @ Wout^T, 64 blocks, 4-way split-K (K=2048)
        if (blk < 64) {
            int nt = blk & 15, ks = blk >> 4;
            int m = warp & 1, nq = warp >> 1;
            int n = nt*64 + nq*16;
            int k0 = ks*512;
            const int K2 = 2*Hdim;
            wmma::fragment<wmma::matrix_a,16,16,16,__half,wmma::row_major> aH, aL;
            wmma::fragment<wmma::matrix_b,16,16,16,__half,wmma::col_major> bH, bL;
            wmma::fragment<wmma::accumulator,16,16,16,float> c;
            wmma::fill_fragment(c, 0.f);
            #pragma unroll 4
            for (int k = k0; k < k0 + 512; k += 16) {
                wmma::load_matrix_sync(aH, d_yH + (size_t)(m*16)*K2 + k, K2);
                wmma::load_matrix_sync(aL, d_yL + (size_t)(m*16)*K2 + k, K2);
                wmma::load_matrix_sync(bH, d_WoutH + (size_t)n*K2 + k, K2);
                wmma::load_matrix_sync(bL, d_WoutL + (size_t)n*K2 + k, K2);
                wmma::mma_sync(c, aH, bH, c);
                wmma::mma_sync(c, aH, bL, c);
                wmma::mma_sync(c, aL, bH, c);
            }
            wmma::store_matrix_sync(d_oP + (size_t)ks*Bdim*Hdim + (size_t)(m*16)*Hdim + n,
                                    c, Hdim, wmma::mem_row_major);
        }
        gbar(mygen);

        // H: finish out = tanh(sum partials); scatter to OutAll + next X feed
        for (int i = gtid; i < Bdim*Hdim; i += SCANB*SCANT) {
            int b = i >> 10, j = i & 1023;
            const size_t PS = (size_t)Bdim*Hdim;
            float v = tanhf(d_oP[i] + d_oP[PS + i] + d_oP[2*PS + i] + d_oP[3*PS + i]);
            d_outf[i] = v;
            d_OutAll[(size_t)t*Bdim*Hdim + i] = __float2half_rn(v);
            if (t + 1 < Tdim) {
                size_t xo = (size_t)((t+1)*Bdim + b)*KX + Edim + j;
                split_write(v, d_XH + xo, d_XL + xo);
            }
        }
        gbar(mygen);
    }
}

// ---------------------------------------------------------------------------
// Generator GEMM with cp.async 2-stage pipeline. BM=128, BN=64, BK=32.
// grid (500, 8), 256 threads.
// ---------------------------------------------------------------------------
#define GLDA 40
__global__ void k_gen(const float* __restrict__ bgen, float* __restrict__ logits) {
    __shared__ __align__(16) __half As[2][128*GLDA];
    __shared__ __align__(16) __half Bs[2][64*GLDA];
    __shared__ float Cs[64*68];
    int nb = blockIdx.x, mb = blockIdx.y;
    int n0 = nb*64, m0 = mb*128;
    int tid = threadIdx.x, warp = tid >> 5;
    int wm = warp >> 1, wn = warp & 1;
    const int K = Hdim;
    wmma::fragment<wmma::accumulator, 16,16,16, float> c[2][2];
    #pragma unroll
    for (int i = 0; i < 2; i++)
        #pragma unroll
        for (int j = 0; j < 2; j++)
            wmma::fill_fragment(c[i][j], 0.f);

    auto loadStage = [&](int stage, int kt) {
        int k0 = kt*32;
        #pragma unroll
        for (int rep = 0; rep < 2; rep++) {
            int ch = tid + rep*256;
            int row = ch >> 2, part = ch & 3;
            cp16(&As[stage][row*GLDA + part*8],
                 &d_OutAll[(size_t)(m0+row)*K + k0 + part*8]);
        }
        {
            int row = tid >> 2, part = tid & 3;
            cp16(&Bs[stage][row*GLDA + part*8],
                 &d_Wgen[(size_t)(n0+row)*K + k0 + part*8]);
        }
    };

    loadStage(0, 0);
    CP_COMMIT();
    const int nIter = K/32;
    for (int kt = 0; kt < nIter; ++kt) {
        int cur = kt & 1;
        if (kt + 1 < nIter) {
            loadStage(cur ^ 1, kt + 1);
            CP_COMMIT();
            CP_WAIT(1);
        } else {
            CP_WAIT(0);
        }
        __syncthreads();
        #pragma unroll
        for (int s = 0; s < 32; s += 16) {
            wmma::fragment<wmma::matrix_a, 16,16,16, __half, wmma::row_major> a[2];
            wmma::fragment<wmma::matrix_b, 16,16,16, __half, wmma::col_major> bfr[2];
            #pragma unroll
            for (int i = 0; i < 2; i++)
                wmma::load_matrix_sync(a[i], &As[cur][(wm*32 + i*16)*GLDA + s], GLDA);
            #pragma unroll
            for (int j = 0; j < 2; j++)
                wmma::load_matrix_sync(bfr[j], &Bs[cur][(wn*32 + j*16)*GLDA + s], GLDA);
            #pragma unroll
            for (int i = 0; i < 2; i++)
                #pragma unroll
                for (int j = 0; j < 2; j++)
                    wmma::mma_sync(c[i][j], a[i], bfr[j], c[i][j]);
        }
        __syncthreads();
    }

    for (int hid = 0; hid < 2; ++hid) {
        if ((wm >> 1) == hid) {
            int wmL = wm & 1;
            #pragma unroll
            for (int i = 0; i < 2; i++)
                #pragma unroll
                for (int j = 0; j < 2; j++)
                    wmma::store_matrix_sync(&Cs[(wmL*32 + i*16)*68 + wn*32 + j*16],
                                            c[i][j], 68, wmma::mem_row_major);
        }
        __syncthreads();
        if (tid < 64) {
            int r = m0 + hid*64 + tid;
            float mx = -1e30f;
            for (int cc = 0; cc < 64; ++cc)
                mx = fmaxf(mx, Cs[tid*68 + cc] + bgen[n0 + cc]);
            float sm = 0.f;
            for (int cc = 0; cc < 64; ++cc)
                sm += expf(Cs[tid*68 + cc] + bgen[n0 + cc] - mx);
            d_partM[(size_t)r*NBLK + nb] = mx;
            d_partS[(size_t)r*NBLK + nb] = sm;
        }
        for (int e = tid; e < 64*64; e += 256) {
            int i = e >> 6, cc = e & 63;
            int r = m0 + hid*64 + i;
            logits[(size_t)r*Vdim + n0 + cc] = Cs[i*68 + cc] + bgen[n0 + cc];
        }
        __syncthreads();
    }
}

// ---------------------------------------------------------------------------
__global__ void k_combine() {
    int r = blockIdx.x, tid = threadIdx.x;
    float m = -1e30f, s = 0.f;
    for (int i = tid; i < NBLK; i += blockDim.x) {
        float mi = d_partM[(size_t)r*NBLK + i];
        float si = d_partS[(size_t)r*NBLK + i];
        float M = fmaxf(m, mi);
        s = s*expf(m - M) + si*expf(mi - M);
        m = M;
    }
    __shared__ float sm[128], ss[128];
    sm[tid] = m; ss[tid] = s;
    __syncthreads();
    for (int o = 64; o; o >>= 1) {
        if (tid < o) {
            float M = fmaxf(sm[tid], sm[tid+o]);
            ss[tid] = ss[tid]*expf(sm[tid] - M) + ss[tid+o]*expf(sm[tid+o] - M);
            sm[tid] = M;
        }
        __syncthreads();
    }
    if (!tid) d_lse[r] = sm[0] + logf(ss[0]);
}

__global__ void k_norm(float* __restrict__ logits) {
    int r = blockIdx.y;
    int i = blockIdx.x*blockDim.x + threadIdx.x;
    if (i < Vdim/4) {
        float4* p = (float4*)(logits + (size_t)r*Vdim);
        float l = d_lse[r];
        float4 v = p[i];
        v.x -= l; v.y -= l; v.z -= l; v.w -= l;
        p[i] = v;
    }
}

__global__ void k_final(float* __restrict__ tail) {
    int i = blockIdx.x*blockDim.x + threadIdx.x;
    const int BH = Bdim*Hdim;
    if (i < BH) {
        tail[i]        = d_h0f[i];
        tail[BH + i]   = d_h1f[i];
        tail[2*BH + i] = d_outf[i];
    }
}

// ---------------------------------------------------------------------------
extern "C" void kernel_launch(void* const* d_in, const int* in_sizes, int n_in,
                              void* d_out, int out_size) {
    (void)in_sizes; (void)n_in; (void)out_size;
    const int*   word_ids = (const int*)  d_in[0];
    const int*   spec_ids = (const int*)  d_in[1];
    const float* word_emb = (const float*)d_in[3];
    const float* spec_emb = (const float*)d_in[4];
    const float* wih0     = (const float*)d_in[5];
    const float* whh0     = (const float*)d_in[6];
    const float* bih0     = (const float*)d_in[7];
    const float* bhh0     = (const float*)d_in[8];
    const float* wih1     = (const float*)d_in[9];
    const float* whh1     = (const float*)d_in[10];
    const float* bih1     = (const float*)d_in[11];
    const float* bhh1     = (const float*)d_in[12];
    const float* Wa       = (const float*)d_in[13];
    const float* Wout     = (const float*)d_in[14];
    const float* Wgen     = (const float*)d_in[15];
    const float* bgen     = (const float*)d_in[16];
    const float* hidden   = (const float*)d_in[17];
    const float* pout     = (const float*)d_in[18];
    const float* context  = (const float*)d_in[19];
    float* outp = (float*)d_out;

    #define SYM(sym, ty, name) ty* name; { void* _p; cudaGetSymbolAddress(&_p, sym); name = (ty*)_p; }
    SYM(d_wih0H, __half, pwih0H)  SYM(d_wih0L, __half, pwih0L)
    SYM(d_whh0H, __half, pwhh0H)  SYM(d_whh0L, __half, pwhh0L)
    SYM(d_wih1H, __half, pwih1H)  SYM(d_wih1L, __half, pwih1L)
    SYM(d_whh1H, __half, pwhh1H)  SYM(d_whh1L, __half, pwhh1L)
    SYM(d_WaH,   __half, pWaH)    SYM(d_WaL,   __half, pWaL)
    SYM(d_WoutH, __half, pWoutH)  SYM(d_WoutL, __half, pWoutL)
    SYM(d_Wgen,  __half, pWgen)
    #undef SYM

    auto cvtS = [&](const float* s, __half* hi, __half* lo, size_t n) {
        k_f2h_split<<<(int)((n + 255)/256), 256>>>(s, hi, lo, (int)n);
    };
    cvtS(wih0, pwih0H, pwih0L, (size_t)G3*KX);
    cvtS(whh0, pwhh0H, pwhh0L, (size_t)G3*Hdim);
    cvtS(wih1, pwih1H, pwih1L, (size_t)G3*Hdim);
    cvtS(whh1, pwhh1H, pwhh1L, (size_t)G3*Hdim);
    cvtS(Wa,   pWaH,   pWaL,   (size_t)Hdim*Hdim);
    cvtS(Wout, pWoutH, pWoutL, (size_t)Hdim*2*Hdim);
    k_f2h<<<(int)(((size_t)Vdim*Hdim/2 + 255)/256), 256>>>(Wgen, pWgen, (int)((size_t)Vdim*Hdim/2));

    k_embed<<<dim3(Tdim, Bdim), 256>>>(word_ids, spec_ids, word_emb, spec_emb);
    k_init<<<(Bdim*Hdim + 255)/256, 256>>>(hidden, pout);
    k_reset<<<1, 1>>>();

    k_scan<<<SCANB, SCANT>>>(bih0, bhh0, bih1, bhh1, context);

    k_gen<<<dim3(NBLK, MROWS/128), 256>>>(bgen, outp);
    k_combine<<<MROWS, 128>>>();
    k_norm<<<dim3(32, MROWS), 256>>>(outp);
    k_final<<<((Bdim*Hdim) + 255)/256, 256>>>(outp + (size_t)MROWS*Vdim);
}